// round 15
// baseline (speedup 1.0000x reference)
#include <cuda_runtime.h>
#include <cuda_fp16.h>
#include <cstdint>

// Problem constants
#define BB 16
#define SS 1024
#define HH 4
#define QDIM 128
#define KDIM 256
#define VDIM 256
#define CH   1024          // H*KD = H*VD
#define MROWS (BB*SS)      // 16384

// ---------------------------------------------------------------------------
// Device scratch (no allocation allowed)
// ---------------------------------------------------------------------------
__device__ __align__(256) float g_TV[MROWS*CH];            // 64 MB fp32 V projection
__device__ __align__(256) float g_colsum4[BB*HH*4*SS];
__device__ __align__(256) float g_meanv[BB*CH];
__device__ __align__(256) float g_WoW1[CH*128];
__device__ __align__(256) float g_bvec[128];

__device__ __align__(256) __half g_Xqh[MROWS*QDIM];
__device__ __align__(256) __half g_Xkh[MROWS*KDIM];
__device__ __align__(256) __half g_Xvh[MROWS*VDIM];
__device__ __align__(256) __half g_Wqth[CH*QDIM], g_Wqtl[CH*QDIM];
__device__ __align__(256) __half g_Wkth[CH*KDIM], g_Wktl[CH*KDIM];
__device__ __align__(256) __half g_Wvth[CH*VDIM], g_Wvtl[CH*VDIM];
__device__ __align__(256) __half g_TQh[MROWS*CH];
__device__ __align__(256) __half g_TKh[MROWS*CH];

// ---------------------------------------------------------------------------
// Low-level helpers (sm_80-era PTX; valid on plain sm_103 target)
// ---------------------------------------------------------------------------
__device__ __forceinline__ uint32_t smem_u32(const void* p) {
    uint32_t a;
    asm("{ .reg .u64 t; cvta.to.shared.u64 t, %1; cvt.u32.u64 %0, t; }"
        : "=r"(a) : "l"(p));
    return a;
}
__device__ __forceinline__ void cp16(uint32_t dst, const void* src) {
    asm volatile("cp.async.cg.shared.global [%0], [%1], 16;"
                 :: "r"(dst), "l"(__cvta_generic_to_global(src)));
}
__device__ __forceinline__ void ldmx4(uint32_t* r, uint32_t addr) {
    asm volatile("ldmatrix.sync.aligned.m8n8.x4.shared.b16 {%0,%1,%2,%3}, [%4];"
                 : "=r"(r[0]), "=r"(r[1]), "=r"(r[2]), "=r"(r[3]) : "r"(addr));
}
__device__ __forceinline__ void mma_f16(float* c, const uint32_t* a, const uint32_t* b) {
    asm volatile("mma.sync.aligned.m16n8k16.row.col.f32.f16.f16.f32 "
                 "{%0,%1,%2,%3}, {%4,%5,%6,%7}, {%8,%9}, {%0,%1,%2,%3};"
                 : "+f"(c[0]), "+f"(c[1]), "+f"(c[2]), "+f"(c[3])
                 : "r"(a[0]), "r"(a[1]), "r"(a[2]), "r"(a[3]), "r"(b[0]), "r"(b[1]));
}

// ---------------------------------------------------------------------------
// Convert fp32 -> fp16 (hi only, vectorized by 4)
// ---------------------------------------------------------------------------
__global__ void __launch_bounds__(256) convert_kernel(
    const float* __restrict__ x, __half* __restrict__ h, int n4)
{
    int i = blockIdx.x * blockDim.x + threadIdx.x;
    if (i >= n4) return;
    float4 v = reinterpret_cast<const float4*>(x)[i];
    reinterpret_cast<__half2*>(h)[i * 2 + 0] =
        __halves2half2(__float2half(v.x), __float2half(v.y));
    reinterpret_cast<__half2*>(h)[i * 2 + 1] =
        __halves2half2(__float2half(v.z), __float2half(v.w));
}

// Transpose + split: W[K,N] -> Wt hi/lo [N,K]
__global__ void __launch_bounds__(256) tsplit_kernel(
    const float* __restrict__ W, __half* __restrict__ th,
    __half* __restrict__ tl, int K, int N)
{
    __shared__ float tile[32][33];
    int tx = threadIdx.x, ty = threadIdx.y;
    int n0 = blockIdx.x * 32, k0 = blockIdx.y * 32;
#pragma unroll
    for (int i = 0; i < 4; i++) {
        int k = k0 + ty + i * 8;
        tile[ty + i * 8][tx] = W[(size_t)k * N + n0 + tx];
    }
    __syncthreads();
#pragma unroll
    for (int i = 0; i < 4; i++) {
        int n = n0 + ty + i * 8;
        int k = k0 + tx;
        float v = tile[tx][ty + i * 8];
        __half h = __float2half(v);
        __half l = __float2half(v - __half2float(h));
        th[(size_t)n * K + k] = h;
        tl[(size_t)n * K + k] = l;
    }
}

// ---------------------------------------------------------------------------
// mma.sync split-fp16 NT GEMM (projections):  C[m,n] = sum_k A[m,k]*B[n,k]
// TERMS==2: D = Ah.Bh + Ah.Bl ; TERMS==1: D = Ah.Bh
// BM=128, BN=128, BK=32, 256 thr, 2-stage cp.async (known-good pipeline).
// ---------------------------------------------------------------------------
#define OFF_BH 8192
#define OFF_BL 16384
#define STG    24576
#define SMEM_TOTAL (2*STG)   // 48 KB

template<int TERMS>
__global__ void __launch_bounds__(256, 2) mma_nt(
    const __half* __restrict__ Ah,
    const __half* __restrict__ Bh, const __half* __restrict__ Bl,
    int K, int lda, int ldb,
    const float* __restrict__ bias, int mode,
    float* __restrict__ Cf, __half* __restrict__ Chi)
{
    extern __shared__ __align__(1024) char smem[];
    uint32_t sb = smem_u32(smem);
    int t = threadIdx.x;
    int lane = t & 31, warp = t >> 5;
    int wm = warp >> 2, wn = warp & 3;
    int m0 = blockIdx.y * 128, n0 = blockIdx.x * 128;

    int r = t & 127, kc2 = (t >> 7) * 2;
    uint32_t so = (uint32_t)(((r >> 3) * 4 + kc2) * 128 + (r & 7) * 16);
    const __half* pAh = Ah + (size_t)(m0 + r) * lda + kc2 * 8;
    const __half* pBh = Bh + (size_t)(n0 + r) * ldb + kc2 * 8;
    const __half* pBl = (TERMS >= 2) ? (Bl + (size_t)(n0 + r) * ldb + kc2 * 8) : nullptr;

    int nch = K >> 5;

    cp16(sb + so,                  pAh);
    cp16(sb + so + 128,            pAh + 8);
    cp16(sb + OFF_BH + so,         pBh);
    cp16(sb + OFF_BH + so + 128,   pBh + 8);
    if (TERMS >= 2) {
        cp16(sb + OFF_BL + so,       pBl);
        cp16(sb + OFF_BL + so + 128, pBl + 8);
    }
    asm volatile("cp.async.commit_group;");

    float acc[4][4][4];
#pragma unroll
    for (int i = 0; i < 4; i++)
#pragma unroll
        for (int j = 0; j < 4; j++)
#pragma unroll
            for (int q = 0; q < 4; q++) acc[i][j][q] = 0.f;

    for (int c = 0; c < nch; c++) {
        if (c + 1 < nch) {
            int kt = (c + 1) << 5;
            uint32_t s1 = sb + ((c + 1) & 1) * STG;
            cp16(s1 + so,                  pAh + kt);
            cp16(s1 + so + 128,            pAh + kt + 8);
            cp16(s1 + OFF_BH + so,         pBh + kt);
            cp16(s1 + OFF_BH + so + 128,   pBh + kt + 8);
            if (TERMS >= 2) {
                cp16(s1 + OFF_BL + so,       pBl + kt);
                cp16(s1 + OFF_BL + so + 128, pBl + kt + 8);
            }
            asm volatile("cp.async.commit_group;");
            asm volatile("cp.async.wait_group 1;");
        } else {
            asm volatile("cp.async.wait_group 0;");
        }
        __syncthreads();

        uint32_t bs = sb + (c & 1) * STG;
#pragma unroll
        for (int s = 0; s < 2; s++) {
            uint32_t af[4][4], bf[4][2], blf[4][2];
            int akcl = s * 2 + (lane >> 4);
            int arl  = (lane >> 3) & 1;
            int lr   = (lane & 7) * 16;
#pragma unroll
            for (int mt = 0; mt < 4; mt++) {
                int rb = wm * 8 + mt * 2 + arl;
                ldmx4(af[mt], bs + (uint32_t)((rb * 4 + akcl) * 128) + lr);
            }
            int bkcl = s * 2 + ((lane >> 3) & 1);
#pragma unroll
            for (int p = 0; p < 2; p++) {
                int rb = wn * 4 + p * 2 + (lane >> 4);
                uint32_t addr = bs + OFF_BH + (uint32_t)((rb * 4 + bkcl) * 128) + lr;
                uint32_t rr[4];
                ldmx4(rr, addr);
                bf[p*2][0]  = rr[0]; bf[p*2][1]  = rr[1];
                bf[p*2+1][0] = rr[2]; bf[p*2+1][1] = rr[3];
                if (TERMS >= 2) {
                    uint32_t rl[4];
                    ldmx4(rl, addr + (OFF_BL - OFF_BH));
                    blf[p*2][0]  = rl[0]; blf[p*2][1]  = rl[1];
                    blf[p*2+1][0] = rl[2]; blf[p*2+1][1] = rl[3];
                }
            }
#pragma unroll
            for (int mt = 0; mt < 4; mt++)
#pragma unroll
                for (int nt = 0; nt < 4; nt++) {
                    mma_f16(acc[mt][nt], af[mt], bf[nt]);
                    if (TERMS >= 2) mma_f16(acc[mt][nt], af[mt], blf[nt]);
                }
        }
        __syncthreads();
    }

#pragma unroll
    for (int mt = 0; mt < 4; mt++)
#pragma unroll
        for (int nt = 0; nt < 4; nt++) {
            int row = m0 + wm * 64 + mt * 16 + (lane >> 2);
            int col = n0 + wn * 32 + nt * 8 + (lane & 3) * 2;
            float b0 = bias ? bias[col] : 0.f;
            float b1 = bias ? bias[col + 1] : 0.f;
            float v0 = acc[mt][nt][0] + b0, v1 = acc[mt][nt][1] + b1;
            float v2 = acc[mt][nt][2] + b0, v3 = acc[mt][nt][3] + b1;
            size_t o0 = (size_t)row * 1024 + col;
            size_t o1 = (size_t)(row + 8) * 1024 + col;
            if (mode == 0) {
                *reinterpret_cast<float2*>(Cf + o0) = make_float2(v0, v1);
                *reinterpret_cast<float2*>(Cf + o1) = make_float2(v2, v3);
            } else {
                *reinterpret_cast<__half2*>(Chi + o0) =
                    __halves2half2(__float2half(v0), __float2half(v1));
                *reinterpret_cast<__half2*>(Chi + o1) =
                    __halves2half2(__float2half(v2), __float2half(v3));
            }
        }
}

// ---------------------------------------------------------------------------
// FUSED scores + softmax + colsum.
// Per CTA: 16 query rows x FULL 1024 key cols for one (b,h).
// D = TQh[16,256] @ TKh^T; softmax over the full row in registers;
// write normalized attn once; accumulate stratified colsum (r = row mod 4).
// 256 threads, 8 warps; warp w owns cols w*128..w*128+127 (16 n8 frags).
// SMEM per stage: A(16x32) at +0 (1KB), B(1024x32) at +1024 (64KB).
// ---------------------------------------------------------------------------
#define FS_STG 66560                 // 1024 + 65536
#define FS_SMEM (2*FS_STG)           // 130 KB

__global__ void __launch_bounds__(256, 1) scores_softmax(
    const __half* __restrict__ TQ, const __half* __restrict__ TK,
    float* __restrict__ attn, float* __restrict__ colsum)
{
    extern __shared__ __align__(1024) char smem[];
    uint32_t sb = smem_u32(smem);
    int t = threadIdx.x;
    int lane = t & 31, warp = t >> 5;
    int m0 = blockIdx.x * 16;
    int z  = blockIdx.y;

    const __half* pA = TQ + (size_t)z * (SS * KDIM);
    const __half* pB = TK + (size_t)z * (SS * KDIM);

    // load maps
    int act = t;                         // A chunk: threads 0..63
    int arow_ld = act >> 2, akc_ld = act & 3;
    uint32_t aso = (uint32_t)(((arow_ld >> 3) * 4 + akc_ld) * 128 + (arow_ld & 7) * 16);
    const __half* pAg = pA + (size_t)(m0 + arow_ld) * KDIM + akc_ld * 8;

    // B chunks: c = t + i*256, i=0..15 ; row=c>>2, kc=c&3
    int brow0 = t >> 2, bkc0 = t & 3;
    const __half* pBg = pB + (size_t)brow0 * KDIM + bkc0 * 8;

    auto load_stage = [&](uint32_t stg, int kt) {
        if (t < 64) cp16(stg + aso, pAg + kt);
#pragma unroll
        for (int i = 0; i < 16; i++) {
            int row = brow0 + i * 64;
            uint32_t so = (uint32_t)(((row >> 3) * 4 + bkc0) * 128 + (row & 7) * 16);
            cp16(stg + 1024 + so, pBg + (size_t)i * 64 * KDIM + kt);
        }
        asm volatile("cp.async.commit_group;");
    };

    load_stage(sb, 0);

    float acc[16][4];
#pragma unroll
    for (int i = 0; i < 16; i++)
#pragma unroll
        for (int q = 0; q < 4; q++) acc[i][q] = 0.f;

    const int nch = KDIM >> 5;   // 8
    for (int c = 0; c < nch; c++) {
        if (c + 1 < nch) {
            load_stage(sb + ((c + 1) & 1) * FS_STG, (c + 1) << 5);
            asm volatile("cp.async.wait_group 1;");
        } else {
            asm volatile("cp.async.wait_group 0;");
        }
        __syncthreads();

        uint32_t bs = sb + (c & 1) * FS_STG;
#pragma unroll
        for (int s = 0; s < 2; s++) {
            int lr = (lane & 7) * 16;
            uint32_t af[4];
            {
                int rg   = (lane >> 3) & 1;
                int akcl = s * 2 + (lane >> 4);
                ldmx4(af, bs + (uint32_t)((rg * 4 + akcl) * 128) + lr);
            }
            int bkcl = s * 2 + ((lane >> 3) & 1);
            uint32_t bf[16][2];
#pragma unroll
            for (int p = 0; p < 8; p++) {
                int rb = warp * 16 + p * 2 + (lane >> 4);
                uint32_t rr[4];
                ldmx4(rr, bs + 1024 + (uint32_t)((rb * 4 + bkcl) * 128) + lr);
                bf[p*2][0]  = rr[0]; bf[p*2][1]  = rr[1];
                bf[p*2+1][0] = rr[2]; bf[p*2+1][1] = rr[3];
            }
#pragma unroll
            for (int nt = 0; nt < 16; nt++)
                mma_f16(acc[nt], af, bf[nt]);
        }
        __syncthreads();
    }

    // ---- softmax epilogue ----
    int r0 = lane >> 2;                  // rows r0 and r0+8
    float* red = reinterpret_cast<float*>(smem);   // 16 x 8 (reuse A area)

    // row max
    float mx0 = -1e30f, mx1 = -1e30f;
#pragma unroll
    for (int nt = 0; nt < 16; nt++) {
        mx0 = fmaxf(mx0, fmaxf(acc[nt][0], acc[nt][1]));
        mx1 = fmaxf(mx1, fmaxf(acc[nt][2], acc[nt][3]));
    }
    mx0 = fmaxf(mx0, __shfl_xor_sync(0xffffffffu, mx0, 1));
    mx0 = fmaxf(mx0, __shfl_xor_sync(0xffffffffu, mx0, 2));
    mx1 = fmaxf(mx1, __shfl_xor_sync(0xffffffffu, mx1, 1));
    mx1 = fmaxf(mx1, __shfl_xor_sync(0xffffffffu, mx1, 2));
    __syncthreads();                      // smem stage reads all done
    if ((lane & 3) == 0) {
        red[r0 * 8 + warp] = mx0;
        red[(r0 + 8) * 8 + warp] = mx1;
    }
    __syncthreads();
    float m0f = -1e30f, m1f = -1e30f;
#pragma unroll
    for (int w = 0; w < 8; w++) {
        m0f = fmaxf(m0f, red[r0 * 8 + w]);
        m1f = fmaxf(m1f, red[(r0 + 8) * 8 + w]);
    }

    // exp + row sum
    float s0 = 0.f, s1 = 0.f;
#pragma unroll
    for (int nt = 0; nt < 16; nt++) {
        acc[nt][0] = __expf(acc[nt][0] - m0f);
        acc[nt][1] = __expf(acc[nt][1] - m0f);
        acc[nt][2] = __expf(acc[nt][2] - m1f);
        acc[nt][3] = __expf(acc[nt][3] - m1f);
        s0 += acc[nt][0] + acc[nt][1];
        s1 += acc[nt][2] + acc[nt][3];
    }
    s0 += __shfl_xor_sync(0xffffffffu, s0, 1);
    s0 += __shfl_xor_sync(0xffffffffu, s0, 2);
    s1 += __shfl_xor_sync(0xffffffffu, s1, 1);
    s1 += __shfl_xor_sync(0xffffffffu, s1, 2);
    __syncthreads();
    if ((lane & 3) == 0) {
        red[r0 * 8 + warp] = s0;
        red[(r0 + 8) * 8 + warp] = s1;
    }
    __syncthreads();
    float sum0 = 0.f, sum1 = 0.f;
#pragma unroll
    for (int w = 0; w < 8; w++) {
        sum0 += red[r0 * 8 + w];
        sum1 += red[(r0 + 8) * 8 + w];
    }
    float inv0 = 1.0f / sum0, inv1 = 1.0f / sum1;

    // normalize, write attn, accumulate colsum
    float* base = attn + (size_t)z * (SS * SS);
    int colb = warp * 128 + (lane & 3) * 2;
    float cs[32];
#pragma unroll
    for (int nt = 0; nt < 16; nt++) {
        float v0 = acc[nt][0] * inv0, v1 = acc[nt][1] * inv0;
        float v2 = acc[nt][2] * inv1, v3 = acc[nt][3] * inv1;
        int col = colb + nt * 8;
        *reinterpret_cast<float2*>(base + (size_t)(m0 + r0) * SS + col) =
            make_float2(v0, v1);
        *reinterpret_cast<float2*>(base + (size_t)(m0 + r0 + 8) * SS + col) =
            make_float2(v2, v3);
        cs[nt * 2 + 0] = v0 + v2;          // rows r0, r0+8 share stratum r0&3
        cs[nt * 2 + 1] = v1 + v3;
    }
    // lanes l and l^16 hold rows differing by 4 -> same stratum, same cols
#pragma unroll
    for (int i = 0; i < 32; i++)
        cs[i] += __shfl_xor_sync(0xffffffffu, cs[i], 16);
    if (lane < 16) {
        int stratum = r0 & 3;              // lane<16 -> r0 = 0..3
        float* cbase = colsum + (size_t)(z * 4 + stratum) * SS;
#pragma unroll
        for (int nt = 0; nt < 16; nt++) {
            atomicAdd(&cbase[colb + nt * 8 + 0], cs[nt * 2 + 0]);
            atomicAdd(&cbase[colb + nt * 8 + 1], cs[nt * 2 + 1]);
        }
    }
}

// ---------------------------------------------------------------------------
// SIMT GEMM kept for the small WoW1 ([1024,2048]@[2048,128])
// ---------------------------------------------------------------------------
__global__ void __launch_bounds__(256) gemm_nn_bias(
    const float* __restrict__ A, const float* __restrict__ B,
    const float* __restrict__ bias, float* __restrict__ C,
    int M, int N, int K)
{
    const int BM = 128, BN = 64, BK = 16;
    __shared__ float As[BK][BM];
    __shared__ float Bs[BK][BN];
    int tid = threadIdx.x;
    int tx = tid & 15, ty = tid >> 4;
    int m0 = blockIdx.y * BM, n0 = blockIdx.x * BN;
    float acc[8][4];
#pragma unroll
    for (int i = 0; i < 8; i++)
#pragma unroll
        for (int j = 0; j < 4; j++) acc[i][j] = 0.f;
    int arow = tid >> 2, acol = (tid & 3) * 4;
    int brow = tid >> 4, bcol = (tid & 15) * 4;
    for (int kt = 0; kt < K; kt += BK) {
#pragma unroll
        for (int p = 0; p < 2; p++) {
            int rr = arow + p * 64;
            float4 v = *reinterpret_cast<const float4*>(&A[(size_t)(m0 + rr) * K + kt + acol]);
            As[acol + 0][rr] = v.x; As[acol + 1][rr] = v.y;
            As[acol + 2][rr] = v.z; As[acol + 3][rr] = v.w;
        }
        {
            float4 v = *reinterpret_cast<const float4*>(&B[(size_t)(kt + brow) * N + n0 + bcol]);
            *reinterpret_cast<float4*>(&Bs[brow][bcol]) = v;
        }
        __syncthreads();
#pragma unroll
        for (int kk = 0; kk < BK; kk++) {
            float a[8], b[4];
#pragma unroll
            for (int i = 0; i < 8; i++) a[i] = As[kk][ty * 8 + i];
#pragma unroll
            for (int j = 0; j < 4; j++) b[j] = Bs[kk][tx * 4 + j];
#pragma unroll
            for (int i = 0; i < 8; i++)
#pragma unroll
                for (int j = 0; j < 4; j++) acc[i][j] = fmaf(a[i], b[j], acc[i][j]);
        }
        __syncthreads();
    }
    float bb[4] = {0.f, 0.f, 0.f, 0.f};
    if (bias) {
#pragma unroll
        for (int j = 0; j < 4; j++) bb[j] = bias[n0 + tx * 4 + j];
    }
#pragma unroll
    for (int i = 0; i < 8; i++) {
        int m = m0 + ty * 8 + i;
        float4 v;
        v.x = acc[i][0] + bb[0]; v.y = acc[i][1] + bb[1];
        v.z = acc[i][2] + bb[2]; v.w = acc[i][3] + bb[3];
        *reinterpret_cast<float4*>(&C[(size_t)m * N + n0 + tx * 4]) = v;
    }
}

__global__ void init_zero()
{
    int i = blockIdx.x * blockDim.x + threadIdx.x;
    if (i < BB * HH * 4 * SS) g_colsum4[i] = 0.f;
    if (i < BB * CH) g_meanv[i] = 0.f;
}

// meanv: grid (BB, 16), 64-k chunks -> 256 CTAs
__global__ void __launch_bounds__(256) meanvec_kernel()
{
    int b = blockIdx.x, kc = blockIdx.y, d = threadIdx.x;
    int k0 = kc * 64;
    float acc0 = 0.f, acc1 = 0.f, acc2 = 0.f, acc3 = 0.f;
    for (int h = 0; h < HH; h++) {
        const float* tv = g_TV + ((size_t)b << 20) + ((size_t)h << 18) + (size_t)k0 * 256;
        const float* cs = g_colsum4 + (size_t)(b * 4 + h) * 4 * SS + k0;
#pragma unroll 4
        for (int k = 0; k < 64; k++) {
            float tvv = tv[(size_t)k * 256 + d];
            acc0 = fmaf(cs[k],          tvv, acc0);
            acc1 = fmaf(cs[SS + k],     tvv, acc1);
            acc2 = fmaf(cs[2 * SS + k], tvv, acc2);
            acc3 = fmaf(cs[3 * SS + k], tvv, acc3);
        }
    }
    const float sc = 1.0f / 1024.0f;
    atomicAdd(&g_meanv[b * CH + 0 * 256 + d], acc0 * sc);
    atomicAdd(&g_meanv[b * CH + 1 * 256 + d], acc1 * sc);
    atomicAdd(&g_meanv[b * CH + 2 * 256 + d], acc2 * sc);
    atomicAdd(&g_meanv[b * CH + 3 * 256 + d], acc3 * sc);
}

__global__ void bvec_kernel(const float* __restrict__ bo,
                            const float* __restrict__ W1,
                            const float* __restrict__ b1)
{
    int j = threadIdx.x;
    float acc = b1[j];
    for (int m = 0; m < 2048; m++) acc = fmaf(bo[m], W1[m * 128 + j], acc);
    g_bvec[j] = acc;
}

__global__ void out_final(float* __restrict__ out)
{
    int b = blockIdx.x, j = threadIdx.x;
    float acc = g_bvec[j];
    const float* mv = g_meanv + b * CH;
    for (int c = 0; c < CH; c++)
        acc = fmaf(mv[c], g_WoW1[c * 128 + j], acc);
    out[b * 128 + j] = acc;
}

// ---------------------------------------------------------------------------
extern "C" void kernel_launch(void* const* d_in, const int* in_sizes, int n_in,
                              void* d_out, int out_size)
{
    const float* query = (const float*)d_in[0];
    const float* key   = (const float*)d_in[1];
    const float* value = (const float*)d_in[2];
    const float* Wq    = (const float*)d_in[3];
    const float* bq    = (const float*)d_in[4];
    const float* Wk    = (const float*)d_in[5];
    const float* bk    = (const float*)d_in[6];
    const float* Wv    = (const float*)d_in[7];
    const float* bv    = (const float*)d_in[8];
    const float* Wo    = (const float*)d_in[9];
    const float* bo    = (const float*)d_in[10];
    const float* W1    = (const float*)d_in[11];
    const float* b1    = (const float*)d_in[12];
    (void)in_sizes; (void)n_in; (void)out_size;

    float* out  = (float*)d_out;
    float* attn = out + (size_t)BB * 128;   // tuple layout: [out, attn]

    void* p;
    cudaGetSymbolAddress(&p, g_TV);      float* TV   = (float*)p;
    cudaGetSymbolAddress(&p, g_colsum4); float* CSUM = (float*)p;
    cudaGetSymbolAddress(&p, g_WoW1);    float* WoW1 = (float*)p;
    __half *Xqh, *Xkh, *Xvh;
    __half *Wqth, *Wqtl, *Wkth, *Wktl, *Wvth, *Wvtl;
    __half *TQh, *TKh;
    cudaGetSymbolAddress(&p, g_Xqh); Xqh = (__half*)p;
    cudaGetSymbolAddress(&p, g_Xkh); Xkh = (__half*)p;
    cudaGetSymbolAddress(&p, g_Xvh); Xvh = (__half*)p;
    cudaGetSymbolAddress(&p, g_Wqth); Wqth = (__half*)p;
    cudaGetSymbolAddress(&p, g_Wqtl); Wqtl = (__half*)p;
    cudaGetSymbolAddress(&p, g_Wkth); Wkth = (__half*)p;
    cudaGetSymbolAddress(&p, g_Wktl); Wktl = (__half*)p;
    cudaGetSymbolAddress(&p, g_Wvth); Wvth = (__half*)p;
    cudaGetSymbolAddress(&p, g_Wvtl); Wvtl = (__half*)p;
    cudaGetSymbolAddress(&p, g_TQh); TQh = (__half*)p;
    cudaGetSymbolAddress(&p, g_TKh); TKh = (__half*)p;

    cudaFuncSetAttribute(mma_nt<2>, cudaFuncAttributeMaxDynamicSharedMemorySize, SMEM_TOTAL);
    cudaFuncSetAttribute(mma_nt<1>, cudaFuncAttributeMaxDynamicSharedMemorySize, SMEM_TOTAL);
    cudaFuncSetAttribute(scores_softmax, cudaFuncAttributeMaxDynamicSharedMemorySize, FS_SMEM);

    dim3 gp(CH / 128, MROWS / 128, 1);

    // 6th launch = K-projection mma_nt<2> (ncu -s 5 -c 1 capture target)
    init_zero<<<1024, 256>>>();                                               // 1
    convert_kernel<<<(MROWS * KDIM / 4 + 255) / 256, 256>>>(key,   Xkh, MROWS * KDIM / 4); // 2
    tsplit_kernel<<<dim3(32, KDIM / 32), dim3(32, 8)>>>(Wk, Wkth, Wktl, KDIM, CH);         // 3
    convert_kernel<<<(MROWS * QDIM / 4 + 255) / 256, 256>>>(query, Xqh, MROWS * QDIM / 4); // 4
    tsplit_kernel<<<dim3(32, QDIM / 32), dim3(32, 8)>>>(Wq, Wqth, Wqtl, QDIM, CH);         // 5
    mma_nt<2><<<gp, 256, SMEM_TOTAL>>>(Xkh, Wkth, Wktl, KDIM, KDIM, KDIM,                  // 6 <- ncu
                                       bk, 1, nullptr, TKh);
    mma_nt<2><<<gp, 256, SMEM_TOTAL>>>(Xqh, Wqth, Wqtl, QDIM, QDIM, QDIM,                  // 7
                                       bq, 1, nullptr, TQh);
    convert_kernel<<<(MROWS * VDIM / 4 + 255) / 256, 256>>>(value, Xvh, MROWS * VDIM / 4); // 8
    tsplit_kernel<<<dim3(32, VDIM / 32), dim3(32, 8)>>>(Wv, Wvth, Wvtl, VDIM, CH);         // 9
    mma_nt<1><<<gp, 256, SMEM_TOTAL>>>(Xvh, Wvth, nullptr, VDIM, VDIM, VDIM,               // 10
                                       bv, 0, TV, nullptr);

    // Small fused tail weights
    gemm_nn_bias<<<dim3(2, 8), 256>>>(Wo, W1, nullptr, WoW1, CH, 128, 2048);
    bvec_kernel<<<1, 128>>>(bo, W1, b1);

    // Fused scores + softmax + colsum: grid (64 m-tiles, 64 bh)
    scores_softmax<<<dim3(SS / 16, BB * HH), 256, FS_SMEM>>>(TQh, TKh, attn, CSUM);

    // Collapse attended-mean and final projections
    meanvec_kernel<<<dim3(BB, 16), 256>>>();
    out_final<<<BB, 128>>>(out);
}

// round 17
// speedup vs baseline: 1.4070x; 1.4070x over previous
#include <cuda_runtime.h>
#include <cuda_fp16.h>
#include <cstdint>

// Problem constants
#define BB 16
#define SS 1024
#define HH 4
#define QDIM 128
#define KDIM 256
#define VDIM 256
#define CH   1024          // H*KD = H*VD
#define MROWS (BB*SS)      // 16384

// ---------------------------------------------------------------------------
// Device scratch (no allocation allowed)
// ---------------------------------------------------------------------------
__device__ __align__(256) float g_TV[MROWS*CH];            // 64 MB fp32 V projection
__device__ __align__(256) float g_colsum4[BB*HH*4*SS];
__device__ __align__(256) float g_meanv[BB*CH];
__device__ __align__(256) float g_WoW1[CH*128];
__device__ __align__(256) float g_bvec[128];

__device__ __align__(256) __half g_Xqh[MROWS*QDIM];
__device__ __align__(256) __half g_Xkh[MROWS*KDIM];
__device__ __align__(256) __half g_Xvh[MROWS*VDIM];
__device__ __align__(256) __half g_Wqth[CH*QDIM], g_Wqtl[CH*QDIM];
__device__ __align__(256) __half g_Wkth[CH*KDIM], g_Wktl[CH*KDIM];
__device__ __align__(256) __half g_Wvth[CH*VDIM], g_Wvtl[CH*VDIM];
__device__ __align__(256) __half g_TQh[MROWS*CH];
__device__ __align__(256) __half g_TKh[MROWS*CH];

// ---------------------------------------------------------------------------
// Low-level helpers (sm_80-era PTX; valid on plain sm_103 target)
// ---------------------------------------------------------------------------
__device__ __forceinline__ uint32_t smem_u32(const void* p) {
    uint32_t a;
    asm("{ .reg .u64 t; cvta.to.shared.u64 t, %1; cvt.u32.u64 %0, t; }"
        : "=r"(a) : "l"(p));
    return a;
}
__device__ __forceinline__ void cp16(uint32_t dst, const void* src) {
    asm volatile("cp.async.cg.shared.global [%0], [%1], 16;"
                 :: "r"(dst), "l"(__cvta_generic_to_global(src)));
}
__device__ __forceinline__ void ldmx4(uint32_t* r, uint32_t addr) {
    asm volatile("ldmatrix.sync.aligned.m8n8.x4.shared.b16 {%0,%1,%2,%3}, [%4];"
                 : "=r"(r[0]), "=r"(r[1]), "=r"(r[2]), "=r"(r[3]) : "r"(addr));
}
__device__ __forceinline__ void mma_f16(float* c, const uint32_t* a, const uint32_t* b) {
    asm volatile("mma.sync.aligned.m16n8k16.row.col.f32.f16.f16.f32 "
                 "{%0,%1,%2,%3}, {%4,%5,%6,%7}, {%8,%9}, {%0,%1,%2,%3};"
                 : "+f"(c[0]), "+f"(c[1]), "+f"(c[2]), "+f"(c[3])
                 : "r"(a[0]), "r"(a[1]), "r"(a[2]), "r"(a[3]), "r"(b[0]), "r"(b[1]));
}

// ---------------------------------------------------------------------------
// Convert fp32 -> fp16 (hi only, vectorized by 4)
// ---------------------------------------------------------------------------
__global__ void __launch_bounds__(256) convert_kernel(
    const float* __restrict__ x, __half* __restrict__ h, int n4)
{
    int i = blockIdx.x * blockDim.x + threadIdx.x;
    if (i >= n4) return;
    float4 v = reinterpret_cast<const float4*>(x)[i];
    reinterpret_cast<__half2*>(h)[i * 2 + 0] =
        __halves2half2(__float2half(v.x), __float2half(v.y));
    reinterpret_cast<__half2*>(h)[i * 2 + 1] =
        __halves2half2(__float2half(v.z), __float2half(v.w));
}

// Transpose + split: W[K,N] -> Wt hi/lo [N,K]
__global__ void __launch_bounds__(256) tsplit_kernel(
    const float* __restrict__ W, __half* __restrict__ th,
    __half* __restrict__ tl, int K, int N)
{
    __shared__ float tile[32][33];
    int tx = threadIdx.x, ty = threadIdx.y;
    int n0 = blockIdx.x * 32, k0 = blockIdx.y * 32;
#pragma unroll
    for (int i = 0; i < 4; i++) {
        int k = k0 + ty + i * 8;
        tile[ty + i * 8][tx] = W[(size_t)k * N + n0 + tx];
    }
    __syncthreads();
#pragma unroll
    for (int i = 0; i < 4; i++) {
        int n = n0 + ty + i * 8;
        int k = k0 + tx;
        float v = tile[tx][ty + i * 8];
        __half h = __float2half(v);
        __half l = __float2half(v - __half2float(h));
        th[(size_t)n * K + k] = h;
        tl[(size_t)n * K + k] = l;
    }
}

// ---------------------------------------------------------------------------
// mma.sync split-fp16 NT GEMM:  C[m,n] = sum_k A[m,k]*B[n,k]
// TERMS==2: D = Ah.Bh + Ah.Bl   (B split; A hi only)
// TERMS==1: D = Ah.Bh           (pure fp16)
// BM=128, BN=128, BK=32, 256 thr (8 warps 2x4, warp tile 64x32), 2-stage
// cp.async (known-good R9/R13 pipeline). SMEM slot order:
// ((row>>3)*4 + kc)*128 + (row&7)*16 -> conflict-free stores + ldmatrix.
// ldc fixed 1024. mode 0: fp32 out (+bias); mode 1: fp16 hi out (+bias).
// ---------------------------------------------------------------------------
#define OFF_BH 8192
#define OFF_BL 16384
#define STG    24576
#define SMEM_TOTAL (2*STG)   // 48 KB

template<int TERMS>
__global__ void __launch_bounds__(256, 2) mma_nt(
    const __half* __restrict__ Ah,
    const __half* __restrict__ Bh, const __half* __restrict__ Bl,
    int K, int lda, int ldb,
    long long strideZ, long long strideCz,
    const float* __restrict__ bias, int mode,
    float* __restrict__ Cf, __half* __restrict__ Chi)
{
    extern __shared__ __align__(1024) char smem[];
    uint32_t sb = smem_u32(smem);
    int t = threadIdx.x;
    int lane = t & 31, warp = t >> 5;
    int wm = warp >> 2, wn = warp & 3;              // 2 x 4 warp grid, warp tile 64x32
    int m0 = blockIdx.y * 128, n0 = blockIdx.x * 128;
    size_t zo = (size_t)blockIdx.z * (size_t)strideZ;

    // cp.async mapping: row r (0..127), two 16B chunks kc2, kc2+1
    int r = t & 127, kc2 = (t >> 7) * 2;
    uint32_t so = (uint32_t)(((r >> 3) * 4 + kc2) * 128 + (r & 7) * 16);
    const __half* pAh = Ah + zo + (size_t)(m0 + r) * lda + kc2 * 8;
    const __half* pBh = Bh + zo + (size_t)(n0 + r) * ldb + kc2 * 8;
    const __half* pBl = (TERMS >= 2) ? (Bl + zo + (size_t)(n0 + r) * ldb + kc2 * 8) : nullptr;

    int nch = K >> 5;

    // prologue: chunk 0 -> stage 0
    cp16(sb + so,                  pAh);
    cp16(sb + so + 128,            pAh + 8);
    cp16(sb + OFF_BH + so,         pBh);
    cp16(sb + OFF_BH + so + 128,   pBh + 8);
    if (TERMS >= 2) {
        cp16(sb + OFF_BL + so,       pBl);
        cp16(sb + OFF_BL + so + 128, pBl + 8);
    }
    asm volatile("cp.async.commit_group;");

    float acc[4][4][4];
#pragma unroll
    for (int i = 0; i < 4; i++)
#pragma unroll
        for (int j = 0; j < 4; j++)
#pragma unroll
            for (int q = 0; q < 4; q++) acc[i][j][q] = 0.f;

    for (int c = 0; c < nch; c++) {
        if (c + 1 < nch) {
            int kt = (c + 1) << 5;
            uint32_t s1 = sb + ((c + 1) & 1) * STG;
            cp16(s1 + so,                  pAh + kt);
            cp16(s1 + so + 128,            pAh + kt + 8);
            cp16(s1 + OFF_BH + so,         pBh + kt);
            cp16(s1 + OFF_BH + so + 128,   pBh + kt + 8);
            if (TERMS >= 2) {
                cp16(s1 + OFF_BL + so,       pBl + kt);
                cp16(s1 + OFF_BL + so + 128, pBl + kt + 8);
            }
            asm volatile("cp.async.commit_group;");
            asm volatile("cp.async.wait_group 1;");
        } else {
            asm volatile("cp.async.wait_group 0;");
        }
        __syncthreads();

        uint32_t bs = sb + (c & 1) * STG;
#pragma unroll
        for (int s = 0; s < 2; s++) {               // two k16 steps per chunk
            uint32_t af[4][4], bf[4][2], blf[4][2];
            int akcl = s * 2 + (lane >> 4);
            int arl  = (lane >> 3) & 1;
            int lr   = (lane & 7) * 16;
#pragma unroll
            for (int mt = 0; mt < 4; mt++) {
                int rb = wm * 8 + mt * 2 + arl;
                ldmx4(af[mt], bs + (uint32_t)((rb * 4 + akcl) * 128) + lr);
            }
            int bkcl = s * 2 + ((lane >> 3) & 1);
#pragma unroll
            for (int p = 0; p < 2; p++) {
                int rb = wn * 4 + p * 2 + (lane >> 4);
                uint32_t addr = bs + OFF_BH + (uint32_t)((rb * 4 + bkcl) * 128) + lr;
                uint32_t rr[4];
                ldmx4(rr, addr);
                bf[p*2][0]  = rr[0]; bf[p*2][1]  = rr[1];
                bf[p*2+1][0] = rr[2]; bf[p*2+1][1] = rr[3];
                if (TERMS >= 2) {
                    uint32_t rl[4];
                    ldmx4(rl, addr + (OFF_BL - OFF_BH));
                    blf[p*2][0]  = rl[0]; blf[p*2][1]  = rl[1];
                    blf[p*2+1][0] = rl[2]; blf[p*2+1][1] = rl[3];
                }
            }
#pragma unroll
            for (int mt = 0; mt < 4; mt++)
#pragma unroll
                for (int nt = 0; nt < 4; nt++) {
                    mma_f16(acc[mt][nt], af[mt], bf[nt]);
                    if (TERMS >= 2) mma_f16(acc[mt][nt], af[mt], blf[nt]);
                }
        }
        __syncthreads();
    }

    // epilogue: registers -> gmem (ldc = 1024)
    size_t cz = (size_t)blockIdx.z * (size_t)strideCz;
#pragma unroll
    for (int mt = 0; mt < 4; mt++)
#pragma unroll
        for (int nt = 0; nt < 4; nt++) {
            int row = m0 + wm * 64 + mt * 16 + (lane >> 2);
            int col = n0 + wn * 32 + nt * 8 + (lane & 3) * 2;
            float b0 = bias ? bias[col] : 0.f;
            float b1 = bias ? bias[col + 1] : 0.f;
            float v0 = acc[mt][nt][0] + b0, v1 = acc[mt][nt][1] + b1;
            float v2 = acc[mt][nt][2] + b0, v3 = acc[mt][nt][3] + b1;
            size_t o0 = (size_t)row * 1024 + col;
            size_t o1 = (size_t)(row + 8) * 1024 + col;
            if (mode == 0) {
                *reinterpret_cast<float2*>(Cf + cz + o0) = make_float2(v0, v1);
                *reinterpret_cast<float2*>(Cf + cz + o1) = make_float2(v2, v3);
            } else {
                *reinterpret_cast<__half2*>(Chi + o0) =
                    __halves2half2(__float2half(v0), __float2half(v1));
                *reinterpret_cast<__half2*>(Chi + o1) =
                    __halves2half2(__float2half(v2), __float2half(v3));
            }
        }
}

// ---------------------------------------------------------------------------
// SIMT GEMM kept for the small WoW1 ([1024,2048]@[2048,128])
// ---------------------------------------------------------------------------
__global__ void __launch_bounds__(256) gemm_nn_bias(
    const float* __restrict__ A, const float* __restrict__ B,
    const float* __restrict__ bias, float* __restrict__ C,
    int M, int N, int K)
{
    const int BM = 128, BN = 64, BK = 16;
    __shared__ float As[BK][BM];
    __shared__ float Bs[BK][BN];
    int tid = threadIdx.x;
    int tx = tid & 15, ty = tid >> 4;
    int m0 = blockIdx.y * BM, n0 = blockIdx.x * BN;
    float acc[8][4];
#pragma unroll
    for (int i = 0; i < 8; i++)
#pragma unroll
        for (int j = 0; j < 4; j++) acc[i][j] = 0.f;
    int arow = tid >> 2, acol = (tid & 3) * 4;
    int brow = tid >> 4, bcol = (tid & 15) * 4;
    for (int kt = 0; kt < K; kt += BK) {
#pragma unroll
        for (int p = 0; p < 2; p++) {
            int rr = arow + p * 64;
            float4 v = *reinterpret_cast<const float4*>(&A[(size_t)(m0 + rr) * K + kt + acol]);
            As[acol + 0][rr] = v.x; As[acol + 1][rr] = v.y;
            As[acol + 2][rr] = v.z; As[acol + 3][rr] = v.w;
        }
        {
            float4 v = *reinterpret_cast<const float4*>(&B[(size_t)(kt + brow) * N + n0 + bcol]);
            *reinterpret_cast<float4*>(&Bs[brow][bcol]) = v;
        }
        __syncthreads();
#pragma unroll
        for (int kk = 0; kk < BK; kk++) {
            float a[8], b[4];
#pragma unroll
            for (int i = 0; i < 8; i++) a[i] = As[kk][ty * 8 + i];
#pragma unroll
            for (int j = 0; j < 4; j++) b[j] = Bs[kk][tx * 4 + j];
#pragma unroll
            for (int i = 0; i < 8; i++)
#pragma unroll
                for (int j = 0; j < 4; j++) acc[i][j] = fmaf(a[i], b[j], acc[i][j]);
        }
        __syncthreads();
    }
    float bb[4] = {0.f, 0.f, 0.f, 0.f};
    if (bias) {
#pragma unroll
        for (int j = 0; j < 4; j++) bb[j] = bias[n0 + tx * 4 + j];
    }
#pragma unroll
    for (int i = 0; i < 8; i++) {
        int m = m0 + ty * 8 + i;
        float4 v;
        v.x = acc[i][0] + bb[0]; v.y = acc[i][1] + bb[1];
        v.z = acc[i][2] + bb[2]; v.w = acc[i][3] + bb[3];
        *reinterpret_cast<float4*>(&C[(size_t)m * N + n0 + tx * 4]) = v;
    }
}

// ---------------------------------------------------------------------------
// In-place softmax over attn rows + stratified column sums (r = s mod 4).
// R13 configuration: grid 256, 8 warps/CTA, warp owns 32 rows.
// ---------------------------------------------------------------------------
__global__ void __launch_bounds__(256) softmax_colsum(
    float* __restrict__ attn, float* __restrict__ colsum)
{
    int blk = blockIdx.x;
    int r = blk & 3;
    int bh = blk >> 2;
    float* base = attn + (size_t)bh * (SS * SS);
    int warp = threadIdx.x >> 5, lane = threadIdx.x & 31;
    float cs[32];
#pragma unroll
    for (int i = 0; i < 32; i++) cs[i] = 0.f;

    for (int i = warp; i < 256; i += 8) {
        int s = r + 4 * i;
        float* row = base + (size_t)s * SS;
        float4 v[8];
#pragma unroll
        for (int j = 0; j < 8; j++)
            v[j] = *reinterpret_cast<float4*>(&row[lane * 4 + 128 * j]);
        float mx = -1e30f;
#pragma unroll
        for (int j = 0; j < 8; j++)
            mx = fmaxf(mx, fmaxf(fmaxf(v[j].x, v[j].y), fmaxf(v[j].z, v[j].w)));
#pragma unroll
        for (int o = 16; o > 0; o >>= 1)
            mx = fmaxf(mx, __shfl_xor_sync(0xffffffffu, mx, o));
        float sum = 0.f;
#pragma unroll
        for (int j = 0; j < 8; j++) {
            v[j].x = __expf(v[j].x - mx); v[j].y = __expf(v[j].y - mx);
            v[j].z = __expf(v[j].z - mx); v[j].w = __expf(v[j].w - mx);
            sum += v[j].x + v[j].y + v[j].z + v[j].w;
        }
#pragma unroll
        for (int o = 16; o > 0; o >>= 1)
            sum += __shfl_xor_sync(0xffffffffu, sum, o);
        float inv = 1.0f / sum;
#pragma unroll
        for (int j = 0; j < 8; j++) {
            v[j].x *= inv; v[j].y *= inv; v[j].z *= inv; v[j].w *= inv;
            cs[4 * j + 0] += v[j].x; cs[4 * j + 1] += v[j].y;
            cs[4 * j + 2] += v[j].z; cs[4 * j + 3] += v[j].w;
            *reinterpret_cast<float4*>(&row[lane * 4 + 128 * j]) = v[j];
        }
    }
    float* cbase = colsum + (size_t)(bh * 4 + r) * SS;
#pragma unroll
    for (int j = 0; j < 8; j++)
#pragma unroll
        for (int q = 0; q < 4; q++)
            atomicAdd(&cbase[lane * 4 + 128 * j + q], cs[4 * j + q]);
}

__global__ void init_zero()
{
    int i = blockIdx.x * blockDim.x + threadIdx.x;
    if (i < BB * HH * 4 * SS) g_colsum4[i] = 0.f;
    if (i < BB * CH) g_meanv[i] = 0.f;
}

// meanv: grid (BB, 16), 64-k chunks -> 256 CTAs
__global__ void __launch_bounds__(256) meanvec_kernel()
{
    int b = blockIdx.x, kc = blockIdx.y, d = threadIdx.x;
    int k0 = kc * 64;
    float acc0 = 0.f, acc1 = 0.f, acc2 = 0.f, acc3 = 0.f;
    for (int h = 0; h < HH; h++) {
        const float* tv = g_TV + ((size_t)b << 20) + ((size_t)h << 18) + (size_t)k0 * 256;
        const float* cs = g_colsum4 + (size_t)(b * 4 + h) * 4 * SS + k0;
#pragma unroll 4
        for (int k = 0; k < 64; k++) {
            float tvv = tv[(size_t)k * 256 + d];
            acc0 = fmaf(cs[k],          tvv, acc0);
            acc1 = fmaf(cs[SS + k],     tvv, acc1);
            acc2 = fmaf(cs[2 * SS + k], tvv, acc2);
            acc3 = fmaf(cs[3 * SS + k], tvv, acc3);
        }
    }
    const float sc = 1.0f / 1024.0f;
    atomicAdd(&g_meanv[b * CH + 0 * 256 + d], acc0 * sc);
    atomicAdd(&g_meanv[b * CH + 1 * 256 + d], acc1 * sc);
    atomicAdd(&g_meanv[b * CH + 2 * 256 + d], acc2 * sc);
    atomicAdd(&g_meanv[b * CH + 3 * 256 + d], acc3 * sc);
}

__global__ void bvec_kernel(const float* __restrict__ bo,
                            const float* __restrict__ W1,
                            const float* __restrict__ b1)
{
    int j = threadIdx.x;
    float acc = b1[j];
    for (int m = 0; m < 2048; m++) acc = fmaf(bo[m], W1[m * 128 + j], acc);
    g_bvec[j] = acc;
}

__global__ void out_final(float* __restrict__ out)
{
    int b = blockIdx.x, j = threadIdx.x;
    float acc = g_bvec[j];
    const float* mv = g_meanv + b * CH;
    for (int c = 0; c < CH; c++)
        acc = fmaf(mv[c], g_WoW1[c * 128 + j], acc);
    out[b * 128 + j] = acc;
}

// ---------------------------------------------------------------------------
extern "C" void kernel_launch(void* const* d_in, const int* in_sizes, int n_in,
                              void* d_out, int out_size)
{
    const float* query = (const float*)d_in[0];
    const float* key   = (const float*)d_in[1];
    const float* value = (const float*)d_in[2];
    const float* Wq    = (const float*)d_in[3];
    const float* bq    = (const float*)d_in[4];
    const float* Wk    = (const float*)d_in[5];
    const float* bk    = (const float*)d_in[6];
    const float* Wv    = (const float*)d_in[7];
    const float* bv    = (const float*)d_in[8];
    const float* Wo    = (const float*)d_in[9];
    const float* bo    = (const float*)d_in[10];
    const float* W1    = (const float*)d_in[11];
    const float* b1    = (const float*)d_in[12];
    (void)in_sizes; (void)n_in; (void)out_size;

    float* out  = (float*)d_out;
    float* attn = out + (size_t)BB * 128;   // tuple layout: [out, attn]

    void* p;
    cudaGetSymbolAddress(&p, g_TV);      float* TV   = (float*)p;
    cudaGetSymbolAddress(&p, g_colsum4); float* CSUM = (float*)p;
    cudaGetSymbolAddress(&p, g_WoW1);    float* WoW1 = (float*)p;
    __half *Xqh, *Xkh, *Xvh;
    __half *Wqth, *Wqtl, *Wkth, *Wktl, *Wvth, *Wvtl;
    __half *TQh, *TKh;
    cudaGetSymbolAddress(&p, g_Xqh); Xqh = (__half*)p;
    cudaGetSymbolAddress(&p, g_Xkh); Xkh = (__half*)p;
    cudaGetSymbolAddress(&p, g_Xvh); Xvh = (__half*)p;
    cudaGetSymbolAddress(&p, g_Wqth); Wqth = (__half*)p;
    cudaGetSymbolAddress(&p, g_Wqtl); Wqtl = (__half*)p;
    cudaGetSymbolAddress(&p, g_Wkth); Wkth = (__half*)p;
    cudaGetSymbolAddress(&p, g_Wktl); Wktl = (__half*)p;
    cudaGetSymbolAddress(&p, g_Wvth); Wvth = (__half*)p;
    cudaGetSymbolAddress(&p, g_Wvtl); Wvtl = (__half*)p;
    cudaGetSymbolAddress(&p, g_TQh); TQh = (__half*)p;
    cudaGetSymbolAddress(&p, g_TKh); TKh = (__half*)p;

    cudaFuncSetAttribute(mma_nt<2>, cudaFuncAttributeMaxDynamicSharedMemorySize, SMEM_TOTAL);
    cudaFuncSetAttribute(mma_nt<1>, cudaFuncAttributeMaxDynamicSharedMemorySize, SMEM_TOTAL);

    dim3 gp(CH / 128, MROWS / 128, 1);

    // 6th launch = K-projection mma_nt<2> (ncu -s 5 -c 1 capture target)
    init_zero<<<1024, 256>>>();                                               // 1
    convert_kernel<<<(MROWS * KDIM / 4 + 255) / 256, 256>>>(key,   Xkh, MROWS * KDIM / 4); // 2
    tsplit_kernel<<<dim3(32, KDIM / 32), dim3(32, 8)>>>(Wk, Wkth, Wktl, KDIM, CH);         // 3
    convert_kernel<<<(MROWS * QDIM / 4 + 255) / 256, 256>>>(query, Xqh, MROWS * QDIM / 4); // 4
    tsplit_kernel<<<dim3(32, QDIM / 32), dim3(32, 8)>>>(Wq, Wqth, Wqtl, QDIM, CH);         // 5
    mma_nt<2><<<gp, 256, SMEM_TOTAL>>>(Xkh, Wkth, Wktl, KDIM, KDIM, KDIM,                  // 6 <- ncu
                                       0, 0, bk, 1, nullptr, TKh);
    mma_nt<2><<<gp, 256, SMEM_TOTAL>>>(Xqh, Wqth, Wqtl, QDIM, QDIM, QDIM,                  // 7
                                       0, 0, bq, 1, nullptr, TQh);
    convert_kernel<<<(MROWS * VDIM / 4 + 255) / 256, 256>>>(value, Xvh, MROWS * VDIM / 4); // 8
    tsplit_kernel<<<dim3(32, VDIM / 32), dim3(32, 8)>>>(Wv, Wvth, Wvtl, VDIM, CH);         // 9
    // V projection: 1-term (proven bit-identical rel_err in R14)
    mma_nt<1><<<gp, 256, SMEM_TOTAL>>>(Xvh, Wvth, nullptr, VDIM, VDIM, VDIM,               // 10
                                       0, 0, bv, 0, TV, nullptr);

    // Small fused tail weights
    gemm_nn_bias<<<dim3(2, 8), 256>>>(Wo, W1, nullptr, WoW1, CH, 128, 2048);
    bvec_kernel<<<1, 128>>>(bo, W1, b1);

    // Scores (1-term pure fp16): per z=(b*4+h), contiguous [1024,256] head block
    dim3 gs(SS / 128, SS / 128, BB * HH);
    mma_nt<1><<<gs, 256, SMEM_TOTAL>>>(TQh, TKh, nullptr, KDIM, KDIM, KDIM,
                                       (long long)SS * KDIM, (long long)SS * SS,
                                       nullptr, 0, attn, nullptr);

    // Softmax in place + stratified column sums (R13 256-grid form)
    softmax_colsum<<<256, 256>>>(attn, CSUM);

    // Collapse attended-mean and final projections
    meanvec_kernel<<<dim3(BB, 16), 256>>>();
    out_final<<<BB, 128>>>(out);
}